// round 13
// baseline (speedup 1.0000x reference)
#include <cuda_runtime.h>
#include <cstdint>

#define NN 50000
#define DD 128
#define ED 32
#define ET 800000
#define BN_EPS 1e-5f

// ---------------- scratch (device globals; no allocation allowed) ----------------
__device__ float g_h[NN * DD];        // scatter-add target (zero-init), then agg
__device__ float g_y1[NN * DD];       // GEMM1 output (pre-BN)
__device__ float g_stats[4 * DD];     // [sum1 | sq1 | sum2 | sq2]

// ---------------- helpers ----------------
__device__ __forceinline__ void ffma2(unsigned long long &d, unsigned long long a, unsigned long long b) {
    asm volatile("fma.rn.f32x2 %0, %1, %2, %0;" : "+l"(d) : "l"(a), "l"(b));
}
__device__ __forceinline__ unsigned long long pack2(float x) {
    unsigned long long r;
    asm("mov.b64 %0, {%1, %1};" : "=l"(r) : "f"(x));
    return r;
}
__device__ __forceinline__ float2 unpack2(unsigned long long v) {
    float2 f;
    asm("mov.b64 {%0, %1}, %2;" : "=f"(f.x), "=f"(f.y) : "l"(v));
    return f;
}
__device__ __forceinline__ void red_v4(float *p, float4 v) {
    asm volatile("red.global.add.v4.f32 [%0], {%1, %2, %3, %4};"
                 :: "l"(p), "f"(v.x), "f"(v.y), "f"(v.z), "f"(v.w) : "memory");
}
__device__ __forceinline__ int ldcs_i(const int *p) {
    int v;
    asm volatile("ld.global.cs.s32 %0, [%1];" : "=r"(v) : "l"(p));
    return v;
}
__device__ __forceinline__ void cp16(uint32_t dst_smem, const float *src) {
    asm volatile("cp.async.cg.shared.global [%0], [%1], 16;"
                 :: "r"(dst_smem), "l"(src) : "memory");
}
__device__ __forceinline__ uint32_t smem_u32(const void *p) {
    uint32_t a;
    asm("{ .reg .u64 t; cvta.to.shared.u64 t, %1; cvt.u32.u64 %0, t; }" : "=r"(a) : "l"(p));
    return a;
}

// ---------------- kernel 1: zero g_h (write-only) ; block 0 zeroes stats --------
__global__ void k_zero() {
    const float4 z = make_float4(0.f, 0.f, 0.f, 0.f);
    for (long i = blockIdx.x * blockDim.x + threadIdx.x; i < NN * DD / 4;
         i += (long)gridDim.x * blockDim.x)
        reinterpret_cast<float4 *>(g_h)[i] = z;
    if (blockIdx.x == 0) {
        for (int t = threadIdx.x; t < 4 * DD; t += 256) g_stats[t] = 0.0f;
    }
}

// ---------------- kernel 2: edge embed + gather + scatter-add -------------------
// (unchanged from R12 — cp.async double-buffered ea, ALU-pipe operand dup)
#define TEB 128
__global__ __launch_bounds__(256, 2) void k_edge(
    const float *__restrict__ x, const int *__restrict__ ei,
    const float *__restrict__ ea, const float *__restrict__ We,
    const float *__restrict__ be)
{
    __shared__ __align__(16) float we_s[ED * DD];       // 16 KB, [k][n]
    __shared__ __align__(16) float ea_s[2][TEB * ED];   // 32 KB, [e][k] plain

    const int tid  = threadIdx.x;
    const int lane = tid & 31;
    const int warp = tid >> 5;
    const int ew   = warp * 16;

    for (int i = tid; i < ED * DD; i += 256) we_s[i] = We[i];

    const float4 be4 = reinterpret_cast<const float4 *>(be)[lane];
    const int ntiles = ET / TEB;   // 6250, exact
    const uint32_t ea_sb[2] = { smem_u32(ea_s[0]), smem_u32(ea_s[1]) };

    {
        const long gb = (long)(blockIdx.x * TEB) * ED;
#pragma unroll
        for (int i = 0; i < 4; i++) {
            int p4 = tid + i * 256;
            cp16(ea_sb[0] + p4 * 16, &ea[gb + p4 * 4]);
        }
        asm volatile("cp.async.commit_group;" ::: "memory");
    }

    int p = 0;
    for (int tile = blockIdx.x; tile < ntiles; tile += gridDim.x) {
        asm volatile("cp.async.wait_group 0;" ::: "memory");
        __syncthreads();

        const int nxt = tile + gridDim.x;
        if (nxt < ntiles) {
            const long gb = (long)(nxt * TEB) * ED;
#pragma unroll
            for (int i = 0; i < 4; i++) {
                int p4 = tid + i * 256;
                cp16(ea_sb[p ^ 1] + p4 * 16, &ea[gb + p4 * 4]);
            }
        }
        asm volatile("cp.async.commit_group;" ::: "memory");

        unsigned long long acc[16][2];
#pragma unroll
        for (int e = 0; e < 16; e++) { acc[e][0] = 0ull; acc[e][1] = 0ull; }

#pragma unroll
        for (int c = 0; c < 8; c++) {            // 4 k per chunk
            ulonglong2 wv[4];
#pragma unroll
            for (int j = 0; j < 4; j++)
                wv[j] = *reinterpret_cast<const ulonglong2 *>(
                    &we_s[(c * 4 + j) * DD + lane * 4]);
#pragma unroll
            for (int e = 0; e < 16; e++) {
                const float4 av = *reinterpret_cast<const float4 *>(
                    &ea_s[p][(ew + e) * ED + c * 4]);   // 16B broadcast
                unsigned long long a;
                a = pack2(av.x); ffma2(acc[e][0], a, wv[0].x); ffma2(acc[e][1], a, wv[0].y);
                a = pack2(av.y); ffma2(acc[e][0], a, wv[1].x); ffma2(acc[e][1], a, wv[1].y);
                a = pack2(av.z); ffma2(acc[e][0], a, wv[2].x); ffma2(acc[e][1], a, wv[2].y);
                a = pack2(av.w); ffma2(acc[e][0], a, wv[3].x); ffma2(acc[e][1], a, wv[3].y);
            }
        }

        const int ebase = tile * TEB;
#pragma unroll
        for (int g = 0; g < 4; g++) {
            int sg[4], dg[4];
            float4 xg[4];
#pragma unroll
            for (int q = 0; q < 4; q++) {
                int eg = ebase + ew + g * 4 + q;
                sg[q] = ldcs_i(&ei[eg]);
                dg[q] = ldcs_i(&ei[ET + eg]);
            }
#pragma unroll
            for (int q = 0; q < 4; q++)
                xg[q] = *reinterpret_cast<const float4 *>(&x[(long)sg[q] * DD + lane * 4]);
#pragma unroll
            for (int q = 0; q < 4; q++) {
                int e = g * 4 + q;
                float2 f01 = unpack2(acc[e][0]);
                float2 f23 = unpack2(acc[e][1]);
                float4 m;
                m.x = xg[q].x + fmaxf(f01.x + be4.x, 0.0f);
                m.y = xg[q].y + fmaxf(f01.y + be4.y, 0.0f);
                m.z = xg[q].z + fmaxf(f23.x + be4.z, 0.0f);
                m.w = xg[q].w + fmaxf(f23.y + be4.w, 0.0f);
                red_v4(&g_h[(long)dg[q] * DD + lane * 4], m);
            }
        }
        p ^= 1;
    }
}

// ---------------- kernel 3/4: GEMM [NN,128]@[128,128] + bias + column stats -----
// PIPELINED: whole W (64 KB) cp.async'd to smem once; next A-tile prefetched
// into registers (transform applied at load) and stored to As after the
// barrier -> A/W LDG latency fully hidden under the FFMA loop.
// Dynamic smem: Ws 64K | As 18K | bnsc/bnsh 1K | cs/cq 1K = 86016 B, 2 CTAs/SM.
#define GSM_WS 0
#define GSM_AS 65536
#define GSM_BN (65536 + 18432)
#define GSM_CS (GSM_BN + 1024)
#define GSM_TOT (GSM_CS + 1024)

template <int PASS>
__global__ __launch_bounds__(256, 2) void k_gemm(
    const float *__restrict__ W, const float *__restrict__ bias,
    const float *__restrict__ gam, const float *__restrict__ bet,
    const float *__restrict__ x, const float *__restrict__ eps,
    float *__restrict__ Yext)
{
    extern __shared__ __align__(16) char dyn[];
    float *Ws   = reinterpret_cast<float *>(dyn + GSM_WS);   // [128][128]
    float *As   = reinterpret_cast<float *>(dyn + GSM_AS);   // [128][36]
    float *bnsc = reinterpret_cast<float *>(dyn + GSM_BN);
    float *bnsh = bnsc + DD;
    float *cs   = reinterpret_cast<float *>(dyn + GSM_CS);
    float *cq   = cs + DD;

    const float *A = (PASS == 0) ? g_h : g_y1;
    float *Y       = (PASS == 0) ? g_y1 : Yext;

    const int tid = threadIdx.x;
    const int tx = tid & 15, ty = tid >> 4;
    const int rowBase = blockIdx.x * DD;
    const float s1 = (PASS == 0) ? (1.0f + eps[0]) : 0.0f;

    // ---- stage whole W asynchronously (4096 float4) ----
    {
        const uint32_t wsb = smem_u32(Ws);
#pragma unroll
        for (int i = 0; i < 16; i++) {
            int p4 = tid + i * 256;
            cp16(wsb + p4 * 16, &W[p4 * 4]);
        }
        asm volatile("cp.async.commit_group;" ::: "memory");
    }

    if (PASS == 1 && tid < DD) {
        float mean = g_stats[tid] * (1.0f / NN);
        float var  = g_stats[DD + tid] * (1.0f / NN) - mean * mean;
        float sc = gam[tid] * rsqrtf(var + BN_EPS);
        bnsc[tid] = sc;
        bnsh[tid] = bet[tid] - mean * sc;
    }
    __syncthreads();   // bnsc visible before any load_tile

    // per-thread A-tile slots: i -> (m = idx>>3, c = idx&7), idx = tid + i*256
    float4 pv[4];
    auto load_tile = [&](int kt) {
#pragma unroll
        for (int i = 0; i < 4; i++) {
            int idx = tid + i * 256;
            int m = idx >> 3, c = idx & 7;
            int row = rowBase + m;
            float4 v = make_float4(0.f, 0.f, 0.f, 0.f);
            if (row < NN) {
                v = *reinterpret_cast<const float4 *>(&A[(long)row * DD + kt + c * 4]);
                if (PASS == 0) {
                    float4 xv = *reinterpret_cast<const float4 *>(&x[(long)row * DD + kt + c * 4]);
                    v.x = fmaf(s1, xv.x, v.x);
                    v.y = fmaf(s1, xv.y, v.y);
                    v.z = fmaf(s1, xv.z, v.z);
                    v.w = fmaf(s1, xv.w, v.w);
                }
            }
            if (PASS == 1) {
                float4 sc = *reinterpret_cast<const float4 *>(&bnsc[kt + c * 4]);
                float4 sh = *reinterpret_cast<const float4 *>(&bnsh[kt + c * 4]);
                v.x = fmaxf(v.x * sc.x + sh.x, 0.0f);
                v.y = fmaxf(v.y * sc.y + sh.y, 0.0f);
                v.z = fmaxf(v.z * sc.z + sh.z, 0.0f);
                v.w = fmaxf(v.w * sc.w + sh.w, 0.0f);
            }
            pv[i] = v;
        }
    };

    load_tile(0);                                      // kt=0 prefetch
    asm volatile("cp.async.wait_group 0;" ::: "memory");
    __syncthreads();                                   // W staged

    unsigned long long acc[8][4];
#pragma unroll
    for (int i = 0; i < 8; i++)
#pragma unroll
        for (int j = 0; j < 4; j++) acc[i][j] = 0ull;

#pragma unroll
    for (int kt = 0; kt < DD; kt += 32) {
        // store prefetched tile
#pragma unroll
        for (int i = 0; i < 4; i++) {
            int idx = tid + i * 256;
            int m = idx >> 3, c = idx & 7;
            *reinterpret_cast<float4 *>(&As[m * 36 + c * 4]) = pv[i];
        }
        __syncthreads();
        if (kt < DD - 32) load_tile(kt + 32);          // hides under FFMA loop

#pragma unroll
        for (int kk = 0; kk < 32; kk++) {
            const float *wr = &Ws[(kt + kk) * DD + tx * 8];
            ulonglong2 b0 = *reinterpret_cast<const ulonglong2 *>(wr);
            ulonglong2 b1 = *reinterpret_cast<const ulonglong2 *>(wr + 4);
#pragma unroll
            for (int i = 0; i < 8; i++) {
                unsigned long long a2 = pack2(As[(ty * 8 + i) * 36 + kk]);
                ffma2(acc[i][0], a2, b0.x);
                ffma2(acc[i][1], a2, b0.y);
                ffma2(acc[i][2], a2, b1.x);
                ffma2(acc[i][3], a2, b1.y);
            }
        }
        __syncthreads();                               // As consumed
    }

    float4 bias0 = *reinterpret_cast<const float4 *>(&bias[tx * 8]);
    float4 bias1 = *reinterpret_cast<const float4 *>(&bias[tx * 8 + 4]);
    float bsum[8], bsq[8];
#pragma unroll
    for (int j = 0; j < 8; j++) { bsum[j] = 0.0f; bsq[j] = 0.0f; }

#pragma unroll
    for (int i = 0; i < 8; i++) {
        int row = rowBase + ty * 8 + i;
        if (row < NN) {
            float2 v0 = unpack2(acc[i][0]);
            float2 v1 = unpack2(acc[i][1]);
            float2 v2 = unpack2(acc[i][2]);
            float2 v3 = unpack2(acc[i][3]);
            float y0 = v0.x + bias0.x, y1v = v0.y + bias0.y;
            float y2 = v1.x + bias0.z, y3 = v1.y + bias0.w;
            float y4 = v2.x + bias1.x, y5 = v2.y + bias1.y;
            float y6 = v3.x + bias1.z, y7 = v3.y + bias1.w;
            *reinterpret_cast<float4 *>(&Y[(long)row * DD + tx * 8]) =
                make_float4(y0, y1v, y2, y3);
            *reinterpret_cast<float4 *>(&Y[(long)row * DD + tx * 8 + 4]) =
                make_float4(y4, y5, y6, y7);
            bsum[0] += y0; bsq[0] += y0 * y0;
            bsum[1] += y1v; bsq[1] += y1v * y1v;
            bsum[2] += y2; bsq[2] += y2 * y2;
            bsum[3] += y3; bsq[3] += y3 * y3;
            bsum[4] += y4; bsq[4] += y4 * y4;
            bsum[5] += y5; bsq[5] += y5 * y5;
            bsum[6] += y6; bsq[6] += y6 * y6;
            bsum[7] += y7; bsq[7] += y7 * y7;
        }
    }

    if (tid < DD) { cs[tid] = 0.0f; cq[tid] = 0.0f; }
    __syncthreads();
#pragma unroll
    for (int j = 0; j < 8; j++) {
        atomicAdd(&cs[tx * 8 + j], bsum[j]);
        atomicAdd(&cq[tx * 8 + j], bsq[j]);
    }
    __syncthreads();
    if (tid < DD) {
        atomicAdd(&g_stats[PASS * 2 * DD + tid], cs[tid]);
        atomicAdd(&g_stats[PASS * 2 * DD + DD + tid], cq[tid]);
    }
}

// ---------------- kernel 5: final BN + ReLU in place on d_out ----------------
__global__ void k_out(float *__restrict__ y, const float *__restrict__ gam,
                      const float *__restrict__ bet) {
    __shared__ __align__(16) float bnsc[DD], bnsh[DD];
    if (threadIdx.x < DD) {
        int t = threadIdx.x;
        float mean = g_stats[2 * DD + t] * (1.0f / NN);
        float var  = g_stats[3 * DD + t] * (1.0f / NN) - mean * mean;
        float sc = gam[t] * rsqrtf(var + BN_EPS);
        bnsc[t] = sc;
        bnsh[t] = bet[t] - mean * sc;
    }
    __syncthreads();
    int i = blockIdx.x * blockDim.x + threadIdx.x;
    if (i >= NN * DD / 4) return;
    float4 v = reinterpret_cast<float4 *>(y)[i];
    int c4 = i & 31;
    float4 sc = *reinterpret_cast<const float4 *>(&bnsc[c4 * 4]);
    float4 sh = *reinterpret_cast<const float4 *>(&bnsh[c4 * 4]);
    v.x = fmaxf(v.x * sc.x + sh.x, 0.0f);
    v.y = fmaxf(v.y * sc.y + sh.y, 0.0f);
    v.z = fmaxf(v.z * sc.z + sh.z, 0.0f);
    v.w = fmaxf(v.w * sc.w + sh.w, 0.0f);
    reinterpret_cast<float4 *>(y)[i] = v;
}

// ---------------- launch ----------------
extern "C" void kernel_launch(void *const *d_in, const int *in_sizes, int n_in,
                              void *d_out, int out_size)
{
    const float *x     = (const float *)d_in[0];
    const int   *ei    = (const int *)d_in[1];
    const float *ea    = (const float *)d_in[2];
    const float *eps   = (const float *)d_in[3];
    const float *We    = (const float *)d_in[4];
    const float *be    = (const float *)d_in[5];
    const float *W1    = (const float *)d_in[6];
    const float *b1    = (const float *)d_in[7];
    const float *g1    = (const float *)d_in[8];
    const float *g1b   = (const float *)d_in[9];
    const float *W2    = (const float *)d_in[10];
    const float *b2    = (const float *)d_in[11];
    const float *g2    = (const float *)d_in[12];
    const float *beta2 = (const float *)d_in[13];
    float *out = (float *)d_out;

    cudaFuncSetAttribute(k_gemm<0>, cudaFuncAttributeMaxDynamicSharedMemorySize, GSM_TOT);
    cudaFuncSetAttribute(k_gemm<1>, cudaFuncAttributeMaxDynamicSharedMemorySize, GSM_TOT);

    k_zero<<<1600, 256>>>();                                  // 1
    k_edge<<<592, 256>>>(x, ei, ea, We, be);                  // 2
    k_gemm<0><<<(NN + DD - 1) / DD, 256, GSM_TOT>>>(W1, b1, nullptr, nullptr, x, eps, nullptr);  // 3
    k_gemm<1><<<(NN + DD - 1) / DD, 256, GSM_TOT>>>(W2, b2, g1, g1b, nullptr, nullptr, out);     // 4
    k_out<<<6250, 256>>>(out, g2, beta2);                     // 5
}

// round 14
// speedup vs baseline: 1.1845x; 1.1845x over previous
#include <cuda_runtime.h>
#include <cstdint>

#define NN 50000
#define DD 128
#define ED 32
#define ET 800000
#define BN_EPS 1e-5f

// ---------------- scratch (device globals; no allocation allowed) ----------------
__device__ float g_h[NN * DD];        // scatter-add target (zero-init), then agg
__device__ float g_y1[NN * DD];       // GEMM1 output (pre-BN)
__device__ float g_stats[4 * DD];     // [sum1 | sq1 | sum2 | sq2]

// ---------------- helpers ----------------
__device__ __forceinline__ void ffma2(unsigned long long &d, unsigned long long a, unsigned long long b) {
    asm volatile("fma.rn.f32x2 %0, %1, %2, %0;" : "+l"(d) : "l"(a), "l"(b));
}
__device__ __forceinline__ unsigned long long pack2(float x) {
    unsigned long long r;
    asm("mov.b64 %0, {%1, %1};" : "=l"(r) : "f"(x));
    return r;
}
__device__ __forceinline__ float2 unpack2(unsigned long long v) {
    float2 f;
    asm("mov.b64 {%0, %1}, %2;" : "=f"(f.x), "=f"(f.y) : "l"(v));
    return f;
}
__device__ __forceinline__ void red_v4(float *p, float4 v) {
    asm volatile("red.global.add.v4.f32 [%0], {%1, %2, %3, %4};"
                 :: "l"(p), "f"(v.x), "f"(v.y), "f"(v.z), "f"(v.w) : "memory");
}
__device__ __forceinline__ int ldcs_i(const int *p) {
    int v;
    asm volatile("ld.global.cs.s32 %0, [%1];" : "=r"(v) : "l"(p));
    return v;
}
__device__ __forceinline__ void cp16(uint32_t dst_smem, const float *src) {
    asm volatile("cp.async.cg.shared.global [%0], [%1], 16;"
                 :: "r"(dst_smem), "l"(src) : "memory");
}
__device__ __forceinline__ uint32_t smem_u32(const void *p) {
    uint32_t a;
    asm("{ .reg .u64 t; cvta.to.shared.u64 t, %1; cvt.u32.u64 %0, t; }" : "=r"(a) : "l"(p));
    return a;
}

// ---------------- kernel 1: zero stats (g_h is zeroed by cudaMemsetAsync) -------
__global__ void k_stats0() {
    g_stats[threadIdx.x] = 0.0f;   // 512 threads
}

// ---------------- kernel 2: edge embed + gather + scatter-add -------------------
// 256 thr (8 warps), tile = 128 edges, 16 edges/warp. Lane l owns cols [4l,4l+3].
// ea staged via cp.async (double-buffered, one tile ahead, ONE barrier/tile).
// {v,v} FFMA2 operands built with pack MOVs on the idle ALU pipe.
// Edge indices: ONE warp-cooperative LDG (lane<16 -> src, lane>=16 -> dst)
// issued BEFORE the FFMA loop; epilogue distributes via SHFL (no L1TEX).
#define TEB 128
__global__ __launch_bounds__(256, 2) void k_edge(
    const float *__restrict__ x, const int *__restrict__ ei,
    const float *__restrict__ ea, const float *__restrict__ We,
    const float *__restrict__ be)
{
    __shared__ __align__(16) float we_s[ED * DD];       // 16 KB, [k][n]
    __shared__ __align__(16) float ea_s[2][TEB * ED];   // 32 KB, [e][k] plain

    const int tid  = threadIdx.x;
    const int lane = tid & 31;
    const int warp = tid >> 5;
    const int ew   = warp * 16;

    for (int i = tid; i < ED * DD; i += 256) we_s[i] = We[i];

    const float4 be4 = reinterpret_cast<const float4 *>(be)[lane];
    const int ntiles = ET / TEB;   // 6250, exact
    const uint32_t ea_sb[2] = { smem_u32(ea_s[0]), smem_u32(ea_s[1]) };

    {
        const long gb = (long)(blockIdx.x * TEB) * ED;
#pragma unroll
        for (int i = 0; i < 4; i++) {
            int p4 = tid + i * 256;
            cp16(ea_sb[0] + p4 * 16, &ea[gb + p4 * 4]);
        }
        asm volatile("cp.async.commit_group;" ::: "memory");
    }

    int p = 0;
    for (int tile = blockIdx.x; tile < ntiles; tile += gridDim.x) {
        const int ebase = tile * TEB;

        // ---- warp-cooperative index load: resolves under staging+FFMA ----
        // lane 0..15: src idx of edge ew+lane; lane 16..31: dst idx of edge ew+lane-16
        int eidx;
        {
            const int q = lane & 15;
            const int *bp = (lane < 16) ? &ei[ebase + ew] : &ei[ET + ebase + ew];
            eidx = ldcs_i(bp + q);
        }

        asm volatile("cp.async.wait_group 0;" ::: "memory");
        __syncthreads();   // buf p data visible; prev reads of buf p done

        const int nxt = tile + gridDim.x;
        if (nxt < ntiles) {
            const long gb = (long)(nxt * TEB) * ED;
#pragma unroll
            for (int i = 0; i < 4; i++) {
                int p4 = tid + i * 256;
                cp16(ea_sb[p ^ 1] + p4 * 16, &ea[gb + p4 * 4]);
            }
        }
        asm volatile("cp.async.commit_group;" ::: "memory");

        // ---- mainloop: 16 edges x 128 cols; dup via ALU MOV, not LDS ----
        unsigned long long acc[16][2];
#pragma unroll
        for (int e = 0; e < 16; e++) { acc[e][0] = 0ull; acc[e][1] = 0ull; }

#pragma unroll
        for (int c = 0; c < 8; c++) {            // 4 k per chunk
            ulonglong2 wv[4];
#pragma unroll
            for (int j = 0; j < 4; j++)
                wv[j] = *reinterpret_cast<const ulonglong2 *>(
                    &we_s[(c * 4 + j) * DD + lane * 4]);
#pragma unroll
            for (int e = 0; e < 16; e++) {
                const float4 av = *reinterpret_cast<const float4 *>(
                    &ea_s[p][(ew + e) * ED + c * 4]);   // 16B broadcast
                unsigned long long a;
                a = pack2(av.x); ffma2(acc[e][0], a, wv[0].x); ffma2(acc[e][1], a, wv[0].y);
                a = pack2(av.y); ffma2(acc[e][0], a, wv[1].x); ffma2(acc[e][1], a, wv[1].y);
                a = pack2(av.z); ffma2(acc[e][0], a, wv[2].x); ffma2(acc[e][1], a, wv[2].y);
                a = pack2(av.w); ffma2(acc[e][0], a, wv[3].x); ffma2(acc[e][1], a, wv[3].y);
            }
        }

        // ---- epilogue: groups of 4 edges; indices via SHFL, gathers batched ----
#pragma unroll
        for (int g = 0; g < 4; g++) {
            int sg[4], dg[4];
            float4 xg[4];
#pragma unroll
            for (int q = 0; q < 4; q++) {
                sg[q] = __shfl_sync(0xffffffffu, eidx, g * 4 + q);
                dg[q] = __shfl_sync(0xffffffffu, eidx, 16 + g * 4 + q);
            }
#pragma unroll
            for (int q = 0; q < 4; q++)
                xg[q] = *reinterpret_cast<const float4 *>(&x[(long)sg[q] * DD + lane * 4]);
#pragma unroll
            for (int q = 0; q < 4; q++) {
                int e = g * 4 + q;
                float2 f01 = unpack2(acc[e][0]);
                float2 f23 = unpack2(acc[e][1]);
                float4 m;
                m.x = xg[q].x + fmaxf(f01.x + be4.x, 0.0f);
                m.y = xg[q].y + fmaxf(f01.y + be4.y, 0.0f);
                m.z = xg[q].z + fmaxf(f23.x + be4.z, 0.0f);
                m.w = xg[q].w + fmaxf(f23.y + be4.w, 0.0f);
                red_v4(&g_h[(long)dg[q] * DD + lane * 4], m);
            }
        }
        p ^= 1;
    }
}

// ---------------- kernel 3/4: GEMM [NN,128]@[128,128] + bias + column stats -----
// (R12 version — measured 58.7 us; whole-W/pv-prefetch variant REGRESSED, reverted)
// PASS 0: A = (1+eps)*x + g_h (residual folded into the A load), Y = g_y1.
// PASS 1: A = relu(bn1(g_y1)) applied on load, Y = out.
template <int PASS>
__global__ __launch_bounds__(256, 2) void k_gemm(
    const float *__restrict__ W, const float *__restrict__ bias,
    const float *__restrict__ gam, const float *__restrict__ bet,
    const float *__restrict__ x, const float *__restrict__ eps,
    float *__restrict__ Yext)
{
    __shared__ __align__(16) float As[DD][36];
    __shared__ __align__(16) float Ws[32][DD];
    __shared__ float cs[DD], cq[DD];
    __shared__ __align__(16) float bnsc[DD], bnsh[DD];

    const float *A = (PASS == 0) ? g_h : g_y1;
    float *Y       = (PASS == 0) ? g_y1 : Yext;

    const int tid = threadIdx.x;
    const int tx = tid & 15, ty = tid >> 4;
    const int rowBase = blockIdx.x * DD;
    const float s1 = (PASS == 0) ? (1.0f + eps[0]) : 0.0f;

    if (PASS == 1 && tid < DD) {
        float mean = g_stats[tid] * (1.0f / NN);
        float var  = g_stats[DD + tid] * (1.0f / NN) - mean * mean;
        float sc = gam[tid] * rsqrtf(var + BN_EPS);
        bnsc[tid] = sc;
        bnsh[tid] = bet[tid] - mean * sc;
    }

    unsigned long long acc[8][4];
#pragma unroll
    for (int i = 0; i < 8; i++)
#pragma unroll
        for (int j = 0; j < 4; j++) acc[i][j] = 0ull;

    for (int kt = 0; kt < DD; kt += 32) {
        __syncthreads();
#pragma unroll
        for (int i = 0; i < 4; i++) {
            int idx = tid + i * 256;
            int m = idx >> 3, c = idx & 7;
            int row = rowBase + m;
            float4 v = make_float4(0.f, 0.f, 0.f, 0.f);
            if (row < NN) {
                v = *reinterpret_cast<const float4 *>(&A[(long)row * DD + kt + c * 4]);
                if (PASS == 0) {
                    float4 xv = *reinterpret_cast<const float4 *>(&x[(long)row * DD + kt + c * 4]);
                    v.x = fmaf(s1, xv.x, v.x);
                    v.y = fmaf(s1, xv.y, v.y);
                    v.z = fmaf(s1, xv.z, v.z);
                    v.w = fmaf(s1, xv.w, v.w);
                }
            }
            if (PASS == 1) {
                float4 sc = *reinterpret_cast<const float4 *>(&bnsc[kt + c * 4]);
                float4 sh = *reinterpret_cast<const float4 *>(&bnsh[kt + c * 4]);
                v.x = fmaxf(v.x * sc.x + sh.x, 0.0f);
                v.y = fmaxf(v.y * sc.y + sh.y, 0.0f);
                v.z = fmaxf(v.z * sc.z + sh.z, 0.0f);
                v.w = fmaxf(v.w * sc.w + sh.w, 0.0f);
            }
            *reinterpret_cast<float4 *>(&As[m][c * 4]) = v;
        }
#pragma unroll
        for (int i = 0; i < 4; i++) {
            int idx = tid + i * 256;
            int r = idx >> 5, c = idx & 31;
            *reinterpret_cast<float4 *>(&Ws[r][c * 4]) =
                *reinterpret_cast<const float4 *>(&W[(long)(kt + r) * DD + c * 4]);
        }
        __syncthreads();

#pragma unroll
        for (int kg = 0; kg < 32; kg += 4) {
            float4 af[8];
#pragma unroll
            for (int i = 0; i < 8; i++)
                af[i] = *reinterpret_cast<const float4 *>(&As[ty * 8 + i][kg]);
#pragma unroll
            for (int j = 0; j < 4; j++) {
                int kk = kg + j;
                ulonglong2 b0 = *reinterpret_cast<const ulonglong2 *>(&Ws[kk][tx * 8]);
                ulonglong2 b1 = *reinterpret_cast<const ulonglong2 *>(&Ws[kk][tx * 8 + 4]);
#pragma unroll
                for (int i = 0; i < 8; i++) {
                    float av = (j == 0) ? af[i].x : (j == 1) ? af[i].y
                              : (j == 2) ? af[i].z : af[i].w;
                    unsigned long long a2 = pack2(av);
                    ffma2(acc[i][0], a2, b0.x);
                    ffma2(acc[i][1], a2, b0.y);
                    ffma2(acc[i][2], a2, b1.x);
                    ffma2(acc[i][3], a2, b1.y);
                }
            }
        }
    }

    float4 bias0 = *reinterpret_cast<const float4 *>(&bias[tx * 8]);
    float4 bias1 = *reinterpret_cast<const float4 *>(&bias[tx * 8 + 4]);
    float bsum[8], bsq[8];
#pragma unroll
    for (int j = 0; j < 8; j++) { bsum[j] = 0.0f; bsq[j] = 0.0f; }

#pragma unroll
    for (int i = 0; i < 8; i++) {
        int row = rowBase + ty * 8 + i;
        if (row < NN) {
            float2 v0 = unpack2(acc[i][0]);
            float2 v1 = unpack2(acc[i][1]);
            float2 v2 = unpack2(acc[i][2]);
            float2 v3 = unpack2(acc[i][3]);
            float y0 = v0.x + bias0.x, y1v = v0.y + bias0.y;
            float y2 = v1.x + bias0.z, y3 = v1.y + bias0.w;
            float y4 = v2.x + bias1.x, y5 = v2.y + bias1.y;
            float y6 = v3.x + bias1.z, y7 = v3.y + bias1.w;
            *reinterpret_cast<float4 *>(&Y[(long)row * DD + tx * 8]) =
                make_float4(y0, y1v, y2, y3);
            *reinterpret_cast<float4 *>(&Y[(long)row * DD + tx * 8 + 4]) =
                make_float4(y4, y5, y6, y7);
            bsum[0] += y0; bsq[0] += y0 * y0;
            bsum[1] += y1v; bsq[1] += y1v * y1v;
            bsum[2] += y2; bsq[2] += y2 * y2;
            bsum[3] += y3; bsq[3] += y3 * y3;
            bsum[4] += y4; bsq[4] += y4 * y4;
            bsum[5] += y5; bsq[5] += y5 * y5;
            bsum[6] += y6; bsq[6] += y6 * y6;
            bsum[7] += y7; bsq[7] += y7 * y7;
        }
    }

    if (tid < DD) { cs[tid] = 0.0f; cq[tid] = 0.0f; }
    __syncthreads();
#pragma unroll
    for (int j = 0; j < 8; j++) {
        atomicAdd(&cs[tx * 8 + j], bsum[j]);
        atomicAdd(&cq[tx * 8 + j], bsq[j]);
    }
    __syncthreads();
    if (tid < DD) {
        atomicAdd(&g_stats[PASS * 2 * DD + tid], cs[tid]);
        atomicAdd(&g_stats[PASS * 2 * DD + DD + tid], cq[tid]);
    }
}

// ---------------- kernel 5: final BN + ReLU in place on d_out ----------------
__global__ void k_out(float *__restrict__ y, const float *__restrict__ gam,
                      const float *__restrict__ bet) {
    __shared__ __align__(16) float bnsc[DD], bnsh[DD];
    if (threadIdx.x < DD) {
        int t = threadIdx.x;
        float mean = g_stats[2 * DD + t] * (1.0f / NN);
        float var  = g_stats[3 * DD + t] * (1.0f / NN) - mean * mean;
        float sc = gam[t] * rsqrtf(var + BN_EPS);
        bnsc[t] = sc;
        bnsh[t] = bet[t] - mean * sc;
    }
    __syncthreads();
    int i = blockIdx.x * blockDim.x + threadIdx.x;
    if (i >= NN * DD / 4) return;
    float4 v = reinterpret_cast<float4 *>(y)[i];
    int c4 = i & 31;
    float4 sc = *reinterpret_cast<const float4 *>(&bnsc[c4 * 4]);
    float4 sh = *reinterpret_cast<const float4 *>(&bnsh[c4 * 4]);
    v.x = fmaxf(v.x * sc.x + sh.x, 0.0f);
    v.y = fmaxf(v.y * sc.y + sh.y, 0.0f);
    v.z = fmaxf(v.z * sc.z + sh.z, 0.0f);
    v.w = fmaxf(v.w * sc.w + sh.w, 0.0f);
    reinterpret_cast<float4 *>(y)[i] = v;
}

// ---------------- launch ----------------
extern "C" void kernel_launch(void *const *d_in, const int *in_sizes, int n_in,
                              void *d_out, int out_size)
{
    const float *x     = (const float *)d_in[0];
    const int   *ei    = (const int *)d_in[1];
    const float *ea    = (const float *)d_in[2];
    const float *eps   = (const float *)d_in[3];
    const float *We    = (const float *)d_in[4];
    const float *be    = (const float *)d_in[5];
    const float *W1    = (const float *)d_in[6];
    const float *b1    = (const float *)d_in[7];
    const float *g1    = (const float *)d_in[8];
    const float *g1b   = (const float *)d_in[9];
    const float *W2    = (const float *)d_in[10];
    const float *b2    = (const float *)d_in[11];
    const float *g2    = (const float *)d_in[12];
    const float *beta2 = (const float *)d_in[13];
    float *out = (float *)d_out;

    void *gh_ptr = nullptr;
    cudaGetSymbolAddress(&gh_ptr, g_h);
    cudaMemsetAsync(gh_ptr, 0, (size_t)NN * DD * sizeof(float));   // 1 (memset node)
    k_stats0<<<1, 512>>>();                                        // 2
    k_edge<<<592, 256>>>(x, ei, ea, We, be);                       // 3
    k_gemm<0><<<(NN + DD - 1) / DD, 256>>>(W1, b1, nullptr, nullptr, x, eps, nullptr);  // 4
    k_gemm<1><<<(NN + DD - 1) / DD, 256>>>(W2, b2, g1, g1b, nullptr, nullptr, out);     // 5
    k_out<<<6250, 256>>>(out, g2, beta2);                          // 6
}